// round 1
// baseline (speedup 1.0000x reference)
#include <cuda_runtime.h>

#define NN 512          // batch size
#define DD 128          // feature dim
#define THREADS 256
#define APC 4           // anchors per CTA
#define NCTA (NN / APC) // 128

__device__ int   g_labels[NN];
__device__ float g_partial[NCTA];
__device__ float g_count[NCTA];

// ---------------------------------------------------------------------------
// Labels may arrive as int32 (JAX x64 disabled) or int64. Detect on-device:
// if int64, every odd 32-bit word in the first 512 words is a zero high-word.
// If int32, odd words are random labels in [0,16) -> all-zero is ~impossible.
// Benign race on `nz` (only ever set to 1) -> deterministic outcome.
// ---------------------------------------------------------------------------
__global__ void decode_labels_kernel(const int* __restrict__ L32) {
    __shared__ int nz;
    int tid = threadIdx.x;             // 256 threads
    if (tid == 0) nz = 0;
    __syncthreads();
    if (L32[2 * tid + 1] != 0) nz = 1; // indices 1..511: in-bounds for both dtypes
    __syncthreads();
    int is64 = (nz == 0);
    for (int j = tid; j < NN; j += blockDim.x)
        g_labels[j] = is64 ? L32[2 * j] : L32[j];
}

// Margin scalar may be float32 or float64. If the first 4 bytes decode to a
// sane float (or exact zero) use it; else reinterpret as double.
__device__ __forceinline__ float read_margin(const void* p) {
    if (p == nullptr) return 0.2f;
    float f = *(const float*)p;
    if (f == 0.0f) return 0.0f;
    float af = fabsf(f);
    if (af > 1e-20f && af < 1e6f) return f;
    return (float)(*(const double*)p);
}

// ---------------------------------------------------------------------------
// One CTA handles APC=4 consecutive anchors. Phase A: distance rows into SMEM
// (x_j streamed once per CTA, reused for all 4 anchors -> 4x less L2 traffic).
// Phase B: compact positive list (d[j]+margin) built serially per anchor
// (deterministic), then each thread owns a fixed set of negatives g and sums
// relu(pos - d[g]). Count is analytic. Fixed-tree block reduction.
// ---------------------------------------------------------------------------
__global__ void __launch_bounds__(THREADS)
triplet_row_kernel(const float* __restrict__ x, const void* __restrict__ margin_ptr) {
    __shared__ float4        xi4[APC][DD / 4];   // x_i + eps, 2 KB
    __shared__ float         d_s[APC][NN];       // distance rows, 8 KB
    __shared__ unsigned char same_s[APC][NN];    // labels[j]==labels[i], 2 KB
    __shared__ float         posd[APC][NN];      // compacted d[pos]+margin, 8 KB
    __shared__ int           np_s[APC];
    __shared__ float         red[THREADS];
    __shared__ int           lab_s[NN];          // 2 KB

    const int tid = threadIdx.x;
    const int ib  = blockIdx.x * APC;
    const float m = read_margin(margin_ptr);

    for (int j = tid; j < NN; j += THREADS) lab_s[j] = g_labels[j];

    // load anchors, pre-shifted by eps:  (a - b + eps) == (a+eps) - b
    for (int t = tid; t < APC * DD; t += THREADS) {
        int a = t / DD, k = t % DD;
        ((float*)&xi4[a][0])[k] = x[(ib + a) * DD + k] + 1e-6f;
    }
    __syncthreads();

    int La[APC];
#pragma unroll
    for (int a = 0; a < APC; a++) La[a] = lab_s[ib + a];

    // ---- Phase A: distance rows ----
    for (int j = tid; j < NN; j += THREADS) {
        const float4* xj = (const float4*)(x + j * DD);
        float acc[APC];
#pragma unroll
        for (int a = 0; a < APC; a++) acc[a] = 0.f;
#pragma unroll 4
        for (int k = 0; k < DD / 4; k++) {
            float4 v = xj[k];
#pragma unroll
            for (int a = 0; a < APC; a++) {
                float4 w = xi4[a][k];
                float t0 = w.x - v.x; acc[a] = fmaf(t0, t0, acc[a]);
                float t1 = w.y - v.y; acc[a] = fmaf(t1, t1, acc[a]);
                float t2 = w.z - v.z; acc[a] = fmaf(t2, t2, acc[a]);
                float t3 = w.w - v.w; acc[a] = fmaf(t3, t3, acc[a]);
            }
        }
        int lj = lab_s[j];
#pragma unroll
        for (int a = 0; a < APC; a++) {
            d_s[a][j]    = sqrtf(acc[a]);
            same_s[a][j] = (unsigned char)(lj == La[a]);
        }
    }
    __syncthreads();

    // ---- compact positive lists (deterministic serial per anchor) ----
    if (tid < APC) {
        int a = tid, self = ib + a, cnt = 0;
        for (int j = 0; j < NN; j++)
            if (same_s[a][j] && j != self) posd[a][cnt++] = d_s[a][j] + m;
        np_s[a] = cnt;
    }
    __syncthreads();

    // ---- Phase B: sum over (pos j, neg g) pairs ----
    float acc = 0.f;
#pragma unroll
    for (int a = 0; a < APC; a++) {
        int np = np_s[a];
        for (int g = tid; g < NN; g += THREADS) {
            if (!same_s[a][g]) {
                float dg = d_s[a][g];
                for (int p = 0; p < np; p++)
                    acc += fmaxf(posd[a][p] - dg, 0.f);
            }
        }
    }

    red[tid] = acc;
    __syncthreads();
    for (int s = THREADS / 2; s > 0; s >>= 1) {
        if (tid < s) red[tid] += red[tid + s];
        __syncthreads();
    }
    if (tid == 0) {
        g_partial[blockIdx.x] = red[0];
        float c = 0.f;
        for (int a = 0; a < APC; a++) {
            float np = (float)np_s[a];
            c += np * (float)(NN - 1 - np_s[a]);  // n_neg = 511 - n_pos
        }
        g_count[blockIdx.x] = c;
    }
}

// ---------------------------------------------------------------------------
// Final deterministic double-precision reduction over 128 CTA partials.
// ---------------------------------------------------------------------------
__global__ void finalize_kernel(float* __restrict__ out, int out_size) {
    __shared__ double sd[NCTA];
    __shared__ double sc[NCTA];
    int tid = threadIdx.x;  // NCTA = 128 threads
    sd[tid] = (double)g_partial[tid];
    sc[tid] = (double)g_count[tid];
    __syncthreads();
    for (int s = NCTA / 2; s > 0; s >>= 1) {
        if (tid < s) { sd[tid] += sd[tid + s]; sc[tid] += sc[tid + s]; }
        __syncthreads();
    }
    if (tid == 0) out[0] = (float)(sd[0] / sc[0]);
    for (int k = tid; k < out_size; k += NCTA)
        if (k > 0) out[k] = 0.f;
}

extern "C" void kernel_launch(void* const* d_in, const int* in_sizes, int n_in,
                              void* d_out, int out_size) {
    const float* x      = (const float*)d_in[0];
    const int*   labels = (const int*)d_in[1];
    const void*  margin = (n_in >= 3) ? d_in[2] : nullptr;

    decode_labels_kernel<<<1, 256>>>(labels);
    triplet_row_kernel<<<NCTA, THREADS>>>(x, margin);
    finalize_kernel<<<1, NCTA>>>((float*)d_out, out_size);
}

// round 2
// speedup vs baseline: 2.2831x; 2.2831x over previous
#include <cuda_runtime.h>

#define NN 512          // batch size
#define DD 128          // feature dim
#define THREADS 512
#define APC 4           // anchors per CTA
#define NCTA (NN / APC) // 128

__device__ float g_partial[NCTA];
__device__ float g_count[NCTA];
__device__ int   g_done = 0;   // reset to 0 by the finalizing CTA each launch

// Margin scalar may arrive as float32 or float64 device scalar.
__device__ __forceinline__ float read_margin(const void* p) {
    if (p == nullptr) return 0.2f;
    float f = *(const float*)p;
    if (f == 0.0f) return 0.0f;
    float af = fabsf(f);
    if (af > 1e-20f && af < 1e6f) return f;
    return (float)(*(const double*)p);
}

// ---------------------------------------------------------------------------
// Single fused kernel. One CTA = 4 consecutive anchors, 512 threads.
//  - labels decoded per-CTA (int32 vs int64 detected from high words)
//  - Phase A: Gram-identity distance rows; 4 lanes cooperate per row so global
//    loads are 64B-contiguous per row-group (8 lines/warp-instr, not 32)
//  - compaction of positives via warp ballot (deterministic order)
//  - Phase B: each thread owns one negative candidate g, sums relu(pos - d_g)
//  - last-arriving CTA does the deterministic fp64 final reduction
// ---------------------------------------------------------------------------
__global__ void __launch_bounds__(THREADS)
fused_triplet_kernel(const float* __restrict__ x, const int* __restrict__ L32,
                     const void* __restrict__ mp, float* __restrict__ out,
                     int out_size)
{
    __shared__ float4        xi4[APC][DD / 4];   // anchors + eps, 2 KB
    __shared__ float         d_s[APC][NN];       // distance rows, 8 KB
    __shared__ unsigned char same_s[APC][NN];    // same-label flags, 2 KB
    __shared__ float         posd[APC][NN];      // compacted d[pos]+margin, 8 KB
    __shared__ int           lab_s[NN];          // 2 KB
    __shared__ int           np_s[APC];
    __shared__ float         na_s[APC];          // ||xi+eps||^2
    __shared__ float         wred[THREADS / 32];
    __shared__ int           flag_s;

    const int tid  = threadIdx.x;
    const int lane = tid & 31;
    const int wid  = tid >> 5;
    const int ib   = blockIdx.x * APC;
    const float m  = read_margin(mp);

    // ---- label dtype detect (int64 => odd 32-bit words all zero) ----
    if (tid == 0) flag_s = 0;
    __syncthreads();
    if (tid < 256 && L32[2 * tid + 1] != 0) flag_s = 1;  // benign OR-race

    // ---- anchors, pre-shifted by eps: (a+eps) - b ----
    {
        int a = tid >> 7, k = tid & 127;  // 512 threads = 4 anchors x 128 dims
        ((float*)&xi4[a][0])[k] = x[(ib + a) * DD + k] + 1e-6f;
    }
    __syncthreads();
    const int is64 = (flag_s == 0);
    lab_s[tid] = is64 ? L32[2 * tid] : L32[tid];

    // ---- anchor norms: warp a handles anchor a ----
    if (wid < APC) {
        const float* w = (const float*)&xi4[wid][0];
        float s = 0.f;
        #pragma unroll
        for (int k = lane; k < DD; k += 32) { float v = w[k]; s = fmaf(v, v, s); }
        #pragma unroll
        for (int o = 16; o > 0; o >>= 1) s += __shfl_xor_sync(0xffffffffu, s, o);
        if (lane == 0) na_s[wid] = s;
    }
    __syncthreads();

    int La[APC];
    #pragma unroll
    for (int a = 0; a < APC; a++) La[a] = lab_s[ib + a];

    // ---- Phase A: distance rows via d^2 = na + nb - 2*dot ----
    // 4 lanes per row: lane-group reads 4 consecutive float4s of the row.
    const int sub = tid & 3;
    #pragma unroll
    for (int pass = 0; pass < 4; pass++) {
        const int r = pass * 128 + (tid >> 2);
        const float4* xr = (const float4*)(x + r * DD);
        float nb = 0.f, a0 = 0.f, a1 = 0.f, a2 = 0.f, a3 = 0.f;
        #pragma unroll
        for (int i = 0; i < 8; i++) {
            int k = sub + 4 * i;
            float4 v  = xr[k];
            nb = fmaf(v.x, v.x, fmaf(v.y, v.y, fmaf(v.z, v.z, fmaf(v.w, v.w, nb))));
            float4 w0 = xi4[0][k];
            a0 = fmaf(w0.x, v.x, fmaf(w0.y, v.y, fmaf(w0.z, v.z, fmaf(w0.w, v.w, a0))));
            float4 w1 = xi4[1][k];
            a1 = fmaf(w1.x, v.x, fmaf(w1.y, v.y, fmaf(w1.z, v.z, fmaf(w1.w, v.w, a1))));
            float4 w2 = xi4[2][k];
            a2 = fmaf(w2.x, v.x, fmaf(w2.y, v.y, fmaf(w2.z, v.z, fmaf(w2.w, v.w, a2))));
            float4 w3 = xi4[3][k];
            a3 = fmaf(w3.x, v.x, fmaf(w3.y, v.y, fmaf(w3.z, v.z, fmaf(w3.w, v.w, a3))));
        }
        // combine partial sums within the 4-lane group (butterfly, all lanes full)
        #pragma unroll
        for (int o = 1; o <= 2; o <<= 1) {
            nb += __shfl_xor_sync(0xffffffffu, nb, o);
            a0 += __shfl_xor_sync(0xffffffffu, a0, o);
            a1 += __shfl_xor_sync(0xffffffffu, a1, o);
            a2 += __shfl_xor_sync(0xffffffffu, a2, o);
            a3 += __shfl_xor_sync(0xffffffffu, a3, o);
        }
        if (sub == 0) {
            const int lr = lab_s[r];
            float dots[APC] = {a0, a1, a2, a3};
            #pragma unroll
            for (int a = 0; a < APC; a++) {
                float d2 = fmaf(-2.f, dots[a], na_s[a] + nb);
                d_s[a][r]    = sqrtf(fmaxf(d2, 0.f));   // clamp self-pair cancellation
                same_s[a][r] = (unsigned char)(lr == La[a]);
            }
        }
    }
    __syncthreads();

    // ---- compact positives: warp a compacts anchor a (ballot, fixed order) ----
    if (wid < APC) {
        const int a = wid, self = ib + a;
        int cnt = 0;
        #pragma unroll
        for (int base = 0; base < NN; base += 32) {
            int j = base + lane;
            bool p = same_s[a][j] && (j != self);
            unsigned msk = __ballot_sync(0xffffffffu, p);
            if (p) posd[a][cnt + __popc(msk & ((1u << lane) - 1u))] = d_s[a][j] + m;
            cnt += __popc(msk);
        }
        if (lane == 0) np_s[a] = cnt;
    }
    __syncthreads();

    // ---- Phase B: thread tid owns candidate negative g = tid ----
    float acc = 0.f;
    #pragma unroll
    for (int a = 0; a < APC; a++) {
        const int np = np_s[a];
        if (!same_s[a][tid]) {
            const float dg = d_s[a][tid];
            float s0 = 0.f, s1 = 0.f;
            int p = 0;
            for (; p + 1 < np; p += 2) {
                s0 += fmaxf(posd[a][p]     - dg, 0.f);
                s1 += fmaxf(posd[a][p + 1] - dg, 0.f);
            }
            if (p < np) s0 += fmaxf(posd[a][p] - dg, 0.f);
            acc += s0 + s1;
        }
    }

    // ---- block reduce (fixed tree) ----
    #pragma unroll
    for (int o = 16; o > 0; o >>= 1) acc += __shfl_xor_sync(0xffffffffu, acc, o);
    if (lane == 0) wred[wid] = acc;
    __syncthreads();
    if (wid == 0) {
        float v = (lane < THREADS / 32) ? wred[lane] : 0.f;
        #pragma unroll
        for (int o = 8; o > 0; o >>= 1) v += __shfl_xor_sync(0xffffffffu, v, o);
        if (lane == 0) {
            g_partial[blockIdx.x] = v;
            float c = 0.f;
            #pragma unroll
            for (int a = 0; a < APC; a++)
                c += (float)np_s[a] * (float)(NN - 1 - np_s[a]);
            g_count[blockIdx.x] = c;
            __threadfence();
            int t = atomicAdd(&g_done, 1);
            flag_s = (t == NCTA - 1) ? 1 : 0;   // am I the last CTA?
        }
    }
    __syncthreads();

    // ---- last CTA: deterministic fp64 final reduction ----
    if (flag_s && wid == 0) {
        double sd = 0.0, sc = 0.0;
        for (int k = lane; k < NCTA; k += 32) {
            sd += (double)g_partial[k];
            sc += (double)g_count[k];
        }
        #pragma unroll
        for (int o = 16; o > 0; o >>= 1) {
            sd += __shfl_xor_sync(0xffffffffu, sd, o);
            sc += __shfl_xor_sync(0xffffffffu, sc, o);
        }
        if (lane == 0) {
            out[0] = (float)(sd / sc);
            for (int k = 1; k < out_size; k++) out[k] = 0.f;
            __threadfence();
            g_done = 0;   // reset for next graph replay
        }
    }
}

extern "C" void kernel_launch(void* const* d_in, const int* in_sizes, int n_in,
                              void* d_out, int out_size) {
    const float* x      = (const float*)d_in[0];
    const int*   labels = (const int*)d_in[1];
    const void*  margin = (n_in >= 3) ? d_in[2] : nullptr;

    fused_triplet_kernel<<<NCTA, THREADS>>>(x, labels, margin,
                                            (float*)d_out, out_size);
}